// round 3
// baseline (speedup 1.0000x reference)
#include <cuda_runtime.h>
#include <cuda_fp16.h>
#include <cstdint>

// ---------------------------------------------------------------------------
// Ragged batched QK^T (static shapes): B=32, H=16, E=64,
// SEQLEN[i]=256+(37i)%257, out = concat_b [H,L_b,L_b], scale = 0.125.
// Plan: (1) one-shot cvt kernel f32 -> f16 (rna) into __device__ scratch,
//       (2) persistent fp16 MMA kernel, cp.async double-buffered pipeline.
// ---------------------------------------------------------------------------
#define NB 32
#define NH 16
#define NE 64
#define BM 128
#define BN 128
#define NTOK 11638
#define ROWH 1024                 // halves per token row (H*E)
#define TPAD 144                  // bytes per smem tile row (128 data + 16 pad)
#define TILEB (BM * TPAD)         // 18432 B per tile
#define PAIRB (2 * TILEB)         // 36864 B per Q+K pair
#define NCTA 296                  // persistent grid (2 per SM)

struct Tables {
    int seqlen[NB];
    int tok_base[NB];
    long long out_base[NB];
    int blk_base[NB + 1];
};

constexpr Tables make_tables() {
    Tables t{};
    int tb = 0; long long ob = 0; int bb = 0;
    for (int i = 0; i < NB; i++) {
        int L = 256 + (i * 37) % 257;
        t.seqlen[i] = L; t.tok_base[i] = tb; t.out_base[i] = ob; t.blk_base[i] = bb;
        int nt = (L + BM - 1) / BM;
        tb += L; ob += (long long)NH * L * L; bb += NH * nt * nt;
    }
    t.blk_base[NB] = bb;
    return t;
}

__constant__ Tables dtab = make_tables();

// fp16 copies of inputs (scratch via __device__ globals — allocation-free)
__device__ __align__(16) __half g_q16[(size_t)NTOK * ROWH];
__device__ __align__(16) __half g_k16[(size_t)NTOK * ROWH];

// ---------------------------------------------------------------------------
__device__ __forceinline__ uint32_t cvta_sm(const void* p) {
    uint32_t a;
    asm("{ .reg .u64 t; cvta.to.shared.u64 t, %1; cvt.u32.u64 %0, t; }"
        : "=r"(a) : "l"(p));
    return a;
}

__device__ __forceinline__ void ldm4(uint32_t* r, uint32_t addr) {
    asm volatile(
        "ldmatrix.sync.aligned.m8n8.x4.shared.b16 {%0,%1,%2,%3}, [%4];"
        : "=r"(r[0]), "=r"(r[1]), "=r"(r[2]), "=r"(r[3]) : "r"(addr));
}

__device__ __forceinline__ void mma_f16(float* d, const uint32_t* a,
                                        uint32_t b0, uint32_t b1) {
    asm volatile(
        "mma.sync.aligned.m16n8k16.row.col.f32.f16.f16.f32 "
        "{%0,%1,%2,%3}, {%4,%5,%6,%7}, {%8,%9}, {%0,%1,%2,%3};"
        : "+f"(d[0]), "+f"(d[1]), "+f"(d[2]), "+f"(d[3])
        : "r"(a[0]), "r"(a[1]), "r"(a[2]), "r"(a[3]), "r"(b0), "r"(b1));
}

__device__ __forceinline__ void cp16(uint32_t dst, const void* src, unsigned sz) {
    asm volatile("cp.async.cg.shared.global [%0], [%1], 16, %2;"
                 :: "r"(dst), "l"(src), "r"(sz));
}

// ---------------------------------------------------------------------------
// Kernel 1: f32 -> f16 (rna) conversion of both inputs.
// grid = NTOK*ROWH/4/256 = 11638 blocks exactly.
__global__ __launch_bounds__(256) void cvt_kernel(
    const float4* __restrict__ a, const float4* __restrict__ b)
{
    size_t i = (size_t)blockIdx.x * 256 + threadIdx.x;
    float4 v = __ldcs(&a[i]);
    __half2 h0 = __floats2half2_rn(v.x, v.y);
    __half2 h1 = __floats2half2_rn(v.z, v.w);
    ((uint2*)g_q16)[i] = make_uint2(*(uint32_t*)&h0, *(uint32_t*)&h1);
    v = __ldcs(&b[i]);
    h0 = __floats2half2_rn(v.x, v.y);
    h1 = __floats2half2_rn(v.z, v.w);
    ((uint2*)g_k16)[i] = make_uint2(*(uint32_t*)&h0, *(uint32_t*)&h1);
}

// ---------------------------------------------------------------------------
struct TileInfo { int L, tokbase, h, qt, kt; long long obase; };

__device__ __forceinline__ TileInfo decode(int bid) {
    int b = 0;
#pragma unroll
    for (int i = 1; i < NB; i++) b += (bid >= dtab.blk_base[i]);
    TileInfo ti;
    ti.L = dtab.seqlen[b];
    const int nt = (ti.L + 127) >> 7;
    int rem = bid - dtab.blk_base[b];
    ti.h = rem / (nt * nt); rem -= ti.h * nt * nt;
    ti.qt = rem / nt; ti.kt = rem - ti.qt * nt;
    ti.tokbase = dtab.tok_base[b];
    ti.obase = dtab.out_base[b] + (long long)ti.h * ti.L * ti.L;
    return ti;
}

// Prefetch one Q+K fp16 tile pair (32KB) into smem via cp.async, zero-filling
// out-of-range rows. 2048 16B chunks over 256 threads = 8 per thread.
__device__ __forceinline__ void prefetch_tile(const TileInfo& ti,
                                              uint32_t dstbase, int tid)
{
    const __half* qb = g_q16 + (size_t)ti.tokbase * ROWH + ti.h * NE;
    const __half* kb = g_k16 + (size_t)ti.tokbase * ROWH + ti.h * NE;
#pragma unroll
    for (int j = 0; j < 4; j++) {
        const int cid = tid + j * 256;
        const int row = cid >> 3, off = cid & 7;

        int grow = ti.qt * BM + row;
        unsigned sz = (grow < ti.L) ? 16u : 0u;
        grow = min(grow, ti.L - 1);
        cp16(dstbase + row * TPAD + off * 16,
             qb + (size_t)grow * ROWH + off * 8, sz);

        grow = ti.kt * BM + row;
        sz = (grow < ti.L) ? 16u : 0u;
        grow = min(grow, ti.L - 1);
        cp16(dstbase + TILEB + row * TPAD + off * 16,
             kb + (size_t)grow * ROWH + off * 8, sz);
    }
}

// ---------------------------------------------------------------------------
// Kernel 2: persistent fp16 tensor-core GEMM, double-buffered pipeline.
__global__ __launch_bounds__(256, 2) void bmm1_fp16(float* __restrict__ out)
{
    extern __shared__ __align__(16) char sm[];
    const uint32_t smbase = cvta_sm(sm);

    const int tid = threadIdx.x;
    const int wid = tid >> 5, l = tid & 31;
    const int wm = wid & 3, wn = wid >> 2;   // 4x2 warp grid, 32m x 64n tiles

    // ldmatrix lane addresses (pair-buffer-relative)
    const uint32_t a_off = (wm * 32 + (l & 7) + ((l >> 3) & 1) * 8) * TPAD
                         + ((l >> 4) & 1) * 16;
    uint32_t b_off[4];
#pragma unroll
    for (int j = 0; j < 4; j++)
        b_off[j] = TILEB
                 + (wn * 64 + j * 16 + (l & 7) + ((l >> 4) & 1) * 8) * TPAD
                 + ((l >> 3) & 1) * 16;

    const int total = dtab.blk_base[NB];   // 5872 tiles

    TileInfo cur = decode(blockIdx.x);
    prefetch_tile(cur, smbase, tid);
    asm volatile("cp.async.commit_group;");

    for (int t = blockIdx.x, i = 0; t < total; t += NCTA, i++) {
        // prefetch next tile into the other buffer (previous iteration's
        // trailing __syncthreads guarantees that buffer is free)
        TileInfo nxt = cur;
        const int tn = t + NCTA;
        if (tn < total) {
            nxt = decode(tn);
            prefetch_tile(nxt, smbase + (1 - (i & 1)) * PAIRB, tid);
        }
        asm volatile("cp.async.commit_group;");
        asm volatile("cp.async.wait_group 1;");   // tile t landed
        __syncthreads();

        const uint32_t pb = smbase + (i & 1) * PAIRB;

        float acc[2][8][4];
#pragma unroll
        for (int mi = 0; mi < 2; mi++)
#pragma unroll
            for (int ni = 0; ni < 8; ni++)
#pragma unroll
                for (int r = 0; r < 4; r++) acc[mi][ni][r] = 0.f;

#pragma unroll
        for (int ks = 0; ks < 4; ks++) {          // 4 k-steps of 16
            const uint32_t koff = ks * 32;        // 16 halves = 32B
            uint32_t A0[4], A1[4], Bf[4][4];
            ldm4(A0, pb + a_off + koff);
            ldm4(A1, pb + a_off + 16 * TPAD + koff);
#pragma unroll
            for (int j = 0; j < 4; j++) ldm4(Bf[j], pb + b_off[j] + koff);
#pragma unroll
            for (int ni = 0; ni < 8; ni++) {
                const uint32_t b0 = Bf[ni >> 1][(ni & 1) * 2];
                const uint32_t b1 = Bf[ni >> 1][(ni & 1) * 2 + 1];
                mma_f16(acc[0][ni], A0, b0, b1);
                mma_f16(acc[1][ni], A1, b0, b1);
            }
        }
        __syncthreads();   // all warps done reading buf before it's reused

        // epilogue: guarded streaming stores (register-only wrt smem,
        // overlaps with the in-flight prefetch)
        const float sc = 0.125f;
        const int q_base = cur.qt * BM + wm * 32 + (l >> 2);
        const int n_base = cur.kt * BN + wn * 64 + 2 * (l & 3);
#pragma unroll
        for (int mi = 0; mi < 2; mi++) {
#pragma unroll
            for (int h2 = 0; h2 < 2; h2++) {
                const int q = q_base + mi * 16 + h2 * 8;
                if (q >= cur.L) continue;
                float* orow = out + cur.obase + (long long)q * cur.L;
#pragma unroll
                for (int ni = 0; ni < 8; ni++) {
                    const int n = n_base + ni * 8;
                    if (n < cur.L)
                        __stcs(orow + n,     acc[mi][ni][h2 * 2 + 0] * sc);
                    if (n + 1 < cur.L)
                        __stcs(orow + n + 1, acc[mi][ni][h2 * 2 + 1] * sc);
                }
            }
        }
        cur = nxt;
    }
}

// ---------------------------------------------------------------------------
extern "C" void kernel_launch(void* const* d_in, const int* in_sizes, int n_in,
                              void* d_out, int out_size)
{
    const float4* q = (const float4*)d_in[0];
    const float4* k = (const float4*)d_in[1];
    float* o = (float*)d_out;

    // 1) convert inputs to fp16 (rna)
    cvt_kernel<<<NTOK, 256>>>(q, k);

    // 2) persistent pipelined fp16 MMA
    constexpr int smem = 2 * PAIRB;   // 73728 B
    cudaFuncSetAttribute(bmm1_fp16,
                         cudaFuncAttributeMaxDynamicSharedMemorySize, smem);
    bmm1_fp16<<<NCTA, 256, smem>>>(o);
}

// round 4
// speedup vs baseline: 1.7597x; 1.7597x over previous
#include <cuda_runtime.h>
#include <cuda_fp16.h>
#include <cstdint>

// ---------------------------------------------------------------------------
// Ragged batched QK^T (static): B=32, H=16, E=64, SEQLEN[i]=256+(37i)%257,
// out = concat_b [H, L_b, L_b], scale = 0.125.
// fp16 m16n8k16 MMA (same 10-bit mantissa as tf32 -> identical rel_err),
// inline f32->fp16 convert at tile load, per-warp staged coalesced epilogue.
// ---------------------------------------------------------------------------
#define NB 32
#define NH 16
#define NE 64
#define BM 128
#define BN 128
#define TPAD 144                  // bytes per fp16 smem tile row (128 + 16 pad)
#define TILEB (BM * TPAD)         // 18432 B
#define WSTRIDE 36                // floats per staging row (32 + 4 pad)
#define WSTAGE (32 * WSTRIDE)     // floats per warp staging buffer (1152)

struct Tables {
    int seqlen[NB];
    int tok_base[NB];
    long long out_base[NB];
    int blk_base[NB + 1];
};

constexpr Tables make_tables() {
    Tables t{};
    int tb = 0; long long ob = 0; int bb = 0;
    for (int i = 0; i < NB; i++) {
        int L = 256 + (i * 37) % 257;
        t.seqlen[i] = L; t.tok_base[i] = tb; t.out_base[i] = ob; t.blk_base[i] = bb;
        int nt = (L + BM - 1) / BM;
        tb += L; ob += (long long)NH * L * L; bb += NH * nt * nt;
    }
    t.blk_base[NB] = bb;
    return t;
}

__constant__ Tables dtab = make_tables();

__device__ __forceinline__ uint32_t cvta_sm(const void* p) {
    uint32_t a;
    asm("{ .reg .u64 t; cvta.to.shared.u64 t, %1; cvt.u32.u64 %0, t; }"
        : "=r"(a) : "l"(p));
    return a;
}

__device__ __forceinline__ void ldm4(uint32_t* r, uint32_t addr) {
    asm volatile(
        "ldmatrix.sync.aligned.m8n8.x4.shared.b16 {%0,%1,%2,%3}, [%4];"
        : "=r"(r[0]), "=r"(r[1]), "=r"(r[2]), "=r"(r[3]) : "r"(addr));
}

__device__ __forceinline__ void mma_f16(float* d, const uint32_t* a,
                                        uint32_t b0, uint32_t b1) {
    asm volatile(
        "mma.sync.aligned.m16n8k16.row.col.f32.f16.f16.f32 "
        "{%0,%1,%2,%3}, {%4,%5,%6,%7}, {%8,%9}, {%0,%1,%2,%3};"
        : "+f"(d[0]), "+f"(d[1]), "+f"(d[2]), "+f"(d[3])
        : "r"(a[0]), "r"(a[1]), "r"(a[2]), "r"(a[3]), "r"(b0), "r"(b1));
}

__global__ __launch_bounds__(256, 2) void bmm1_fp16(
    const float* __restrict__ Q,
    const float* __restrict__ K,
    float* __restrict__ out)
{
    extern __shared__ __align__(16) char sm[];
    char* smQ = sm;                // fp16 [128][TPAD bytes]
    char* smK = sm + TILEB;
    float* stage = (float*)(sm + 2 * TILEB);

    const int bid = blockIdx.x;

    // ---- locate (batch, head, qtile, ktile) ----
    int b = 0;
#pragma unroll
    for (int i = 1; i < NB; i++) b += (bid >= dtab.blk_base[i]);
    const int L  = dtab.seqlen[b];
    const int nt = (L + 127) >> 7;
    int rem = bid - dtab.blk_base[b];
    const int h  = rem / (nt * nt);
    rem -= h * (nt * nt);
    const int qt = rem / nt;
    const int kt = rem - qt * nt;

    const int tid = threadIdx.x;
    const long long rowstride = (long long)NH * NE;   // 1024 floats/token
    const float* qbase = Q + (long long)dtab.tok_base[b] * rowstride + h * NE;
    const float* kbase = K + (long long)dtab.tok_base[b] * rowstride + h * NE;

    // ---- global f32 -> smem fp16 tiles (inline rn convert, zero-fill) ----
    {
        const int c4 = tid & 15;       // float4 chunk within 64-float row
        const int rl = tid >> 4;       // row within 16-row pass
#pragma unroll
        for (int g = 0; g < 8; g++) {
            const int m = rl + g * 16;

            const int qrow = qt * BM + m;
            float4 v = (qrow < L)
                ? *(const float4*)(qbase + (long long)qrow * rowstride + c4 * 4)
                : make_float4(0.f, 0.f, 0.f, 0.f);
            __half2 h0 = __floats2half2_rn(v.x, v.y);
            __half2 h1 = __floats2half2_rn(v.z, v.w);
            *(uint2*)(smQ + m * TPAD + c4 * 8) =
                make_uint2(*(uint32_t*)&h0, *(uint32_t*)&h1);

            const int krow = kt * BN + m;
            float4 u = (krow < L)
                ? *(const float4*)(kbase + (long long)krow * rowstride + c4 * 4)
                : make_float4(0.f, 0.f, 0.f, 0.f);
            h0 = __floats2half2_rn(u.x, u.y);
            h1 = __floats2half2_rn(u.z, u.w);
            *(uint2*)(smK + m * TPAD + c4 * 8) =
                make_uint2(*(uint32_t*)&h0, *(uint32_t*)&h1);
        }
    }
    __syncthreads();

    // ---- warp layout: 8 warps = 4(m) x 2(n); warp tile 32m x 64n ----
    const int wid = tid >> 5, l = tid & 31;
    const int wm = wid & 3, wn = wid >> 2;

    const uint32_t smbase = cvta_sm(sm);
    const uint32_t a_off = smbase
        + (wm * 32 + (l & 7) + ((l >> 3) & 1) * 8) * TPAD
        + ((l >> 4) & 1) * 16;
    uint32_t b_off[4];
#pragma unroll
    for (int j = 0; j < 4; j++)
        b_off[j] = smbase + TILEB
            + (wn * 64 + j * 16 + (l & 7) + ((l >> 4) & 1) * 8) * TPAD
            + ((l >> 3) & 1) * 16;

    float acc[2][8][4];
#pragma unroll
    for (int mi = 0; mi < 2; mi++)
#pragma unroll
        for (int ni = 0; ni < 8; ni++)
#pragma unroll
            for (int r = 0; r < 4; r++) acc[mi][ni][r] = 0.f;

#pragma unroll
    for (int ks = 0; ks < 4; ks++) {          // 4 k-steps of 16
        const uint32_t koff = ks * 32;        // 16 halves = 32B
        uint32_t A0[4], A1[4], Bf[4][4];
        ldm4(A0, a_off + koff);
        ldm4(A1, a_off + 16 * TPAD + koff);
#pragma unroll
        for (int j = 0; j < 4; j++) ldm4(Bf[j], b_off[j] + koff);
#pragma unroll
        for (int ni = 0; ni < 8; ni++) {
            const uint32_t b0 = Bf[ni >> 1][(ni & 1) * 2];
            const uint32_t b1 = Bf[ni >> 1][(ni & 1) * 2 + 1];
            mma_f16(acc[0][ni], A0, b0, b1);
            mma_f16(acc[1][ni], A1, b0, b1);
        }
    }

    // ---- per-warp staged epilogue: coalesced row-major stores ----
    const float sc = 0.125f;
    float* wst = stage + wid * WSTAGE;
    const int q0w = qt * BM + wm * 32;
    const int n0w = kt * BN + wn * 64;
    const long long obase = dtab.out_base[b] + (long long)h * L * L;
    const int rmax = min(32, L - q0w);

#pragma unroll
    for (int half = 0; half < 2; half++) {
        __syncwarp();
#pragma unroll
        for (int mi = 0; mi < 2; mi++)
#pragma unroll
            for (int h2 = 0; h2 < 2; h2++)
#pragma unroll
                for (int ni4 = 0; ni4 < 4; ni4++) {
                    const int ni = half * 4 + ni4;
                    const int r = mi * 16 + h2 * 8 + (l >> 2);
                    const int col = 2 * (l & 3) + 8 * ni4;
                    *(float2*)&wst[r * WSTRIDE + col] =
                        make_float2(acc[mi][ni][h2 * 2 + 0] * sc,
                                    acc[mi][ni][h2 * 2 + 1] * sc);
                }
        __syncwarp();

        const int n = n0w + half * 32 + l;
        const bool nv = n < L;
        const float* src = wst + l;
        float* dst = out + obase + (long long)q0w * L + n;
#pragma unroll 8
        for (int r = 0; r < rmax; r++) {
            const float v = src[r * WSTRIDE];
            if (nv) dst[(long long)r * L] = v;
        }
    }
}

extern "C" void kernel_launch(void* const* d_in, const int* in_sizes, int n_in,
                              void* d_out, int out_size)
{
    const float* q = (const float*)d_in[0];
    const float* k = (const float*)d_in[1];
    float* o = (float*)d_out;

    constexpr Tables ht = make_tables();
    const int nblocks = ht.blk_base[NB];     // 5872

    constexpr int smem = 2 * TILEB + 8 * WSTAGE * (int)sizeof(float); // 73728
    cudaFuncSetAttribute(bmm1_fp16,
                         cudaFuncAttributeMaxDynamicSharedMemorySize, smem);
    bmm1_fp16<<<nblocks, 256, smem>>>(q, k, o);
}